// round 5
// baseline (speedup 1.0000x reference)
#include <cuda_runtime.h>
#include <cuda_bf16.h>
#include <math.h>
#include <stdint.h>

#define Bn   8
#define Ln   9216
#define Cn   512
#define Hn   8
#define DK   64
#define HID  2048
#define Mrows (Bn*Ln)          // 73728

// ---------------- scratch (device globals: no runtime allocation) ----------
__device__ float          g_xn  [Mrows*Cn];   // fp32 xn (reproj epilogue addend)
__device__ __nv_bfloat16  g_xnb [Mrows*Cn];   // bf16 xn (GEMM A)
__device__ __nv_bfloat16  g_vnb [Mrows*Cn];   // bf16 vn (GEMM A)
__device__ float          g_q   [Mrows*Cn];
__device__ float          g_k   [Mrows*Cn];
__device__ float          g_val [Mrows*Cn];
__device__ float          g_ctx [Bn*Hn*DK*DK];
__device__ __nv_bfloat16  g_aggT[Mrows*Cn];   // (B, L, C) bf16 (reproj B operand)
__device__ float          g_attn[Mrows*Cn];   // reproj + xn, flat == (M, C) reinterpret
__device__ float          g_x1  [Mrows*Cn];
__device__ __nv_bfloat16  g_x1nb[Mrows*Cn];   // bf16 LN2 out (fc1 A)
__device__ __nv_bfloat16  g_h1b [Mrows*HID];  // bf16 gelu(fc1) (fc2 A)
// bf16 weights
__device__ __nv_bfloat16  g_wqb [Cn*Cn];
__device__ __nv_bfloat16  g_wkb [Cn*Cn];
__device__ __nv_bfloat16  g_wvb [Cn*Cn];
__device__ __nv_bfloat16  g_wrb [Cn*Cn];
__device__ __nv_bfloat16  g_f1b [HID*Cn];
__device__ __nv_bfloat16  g_f2b [Cn*HID];

// ---------------- asm helpers ------------------------------------------------
__device__ __forceinline__ uint32_t smem_u32(const void* p) {
    uint32_t a;
    asm("{ .reg .u64 t; cvta.to.shared.u64 t, %1; cvt.u32.u64 %0, t; }" : "=r"(a) : "l"(p));
    return a;
}
__device__ __forceinline__ void ldsm4(uint32_t* r, uint32_t a) {
    asm volatile("ldmatrix.sync.aligned.m8n8.x4.shared.b16 {%0,%1,%2,%3}, [%4];"
        : "=r"(r[0]), "=r"(r[1]), "=r"(r[2]), "=r"(r[3]) : "r"(a));
}
__device__ __forceinline__ void mma_bf16(float* c, const uint32_t* a, const uint32_t* b) {
    asm volatile("mma.sync.aligned.m16n8k16.row.col.f32.bf16.bf16.f32 "
        "{%0,%1,%2,%3}, {%4,%5,%6,%7}, {%8,%9}, {%0,%1,%2,%3};"
        : "+f"(c[0]), "+f"(c[1]), "+f"(c[2]), "+f"(c[3])
        : "r"(a[0]), "r"(a[1]), "r"(a[2]), "r"(a[3]), "r"(b[0]), "r"(b[1]));
}
__device__ __forceinline__ void cp16(uint32_t dst, const void* src) {
    asm volatile("cp.async.cg.shared.global [%0], [%1], 16;" :: "r"(dst), "l"(src));
}
#define CP_COMMIT() asm volatile("cp.async.commit_group;" ::: "memory")
#define CP_WAIT2()  asm volatile("cp.async.wait_group 2;" ::: "memory")

// smem tile geometry: rows of 32 bf16 (64B) padded to 80B -> conflict-free LDSM
#define ROWB   80
#define STG_A  (128*ROWB)          // 10240
#define STG_B  (256*ROWB)          // 20480
#define STG    (STG_A + STG_B)     // 30720 per stage
#define NST    4
#define SMEM_REQ (NST*STG)         // 122880

// ---------------- misc device helpers ---------------------------------------
__device__ __forceinline__ float gelu_exact(float x) {
    return 0.5f * x * (1.0f + erff(x * 0.70710678118654752f));
}

__device__ __forceinline__ float blockReduceSum256(float v, float* s8, int tid) {
    #pragma unroll
    for (int o = 16; o > 0; o >>= 1) v += __shfl_xor_sync(0xffffffffu, v, o);
    int lane = tid & 31, w = tid >> 5;
    if (lane == 0) s8[w] = v;
    __syncthreads();
    if (w == 0) {
        v = (lane < 8) ? s8[lane] : 0.f;
        #pragma unroll
        for (int o = 4; o > 0; o >>= 1) v += __shfl_xor_sync(0xffffffffu, v, o);
        if (lane == 0) s8[0] = v;
    }
    __syncthreads();
    float r = s8[0];
    __syncthreads();
    return r;
}

// ---------------- bf16 GEMM (NT): C[M,N] = A[M,K]·W[N,K]^T + epilogue -------
// CTA 128x256, warp tile 64x64 (8 warps), K-chunk 32, 4-stage cp.async,
// ldmatrix + mma m16n8k16, ONE __syncthreads per chunk.
// EPI: 0 bias(n) -> f32        1 bias(n)+gelu -> bf16
//      2 bias(n)+res -> f32    3 reproj: br(m) + xn gather, out stride Ln -> f32
template<int EPI>
__global__ __launch_bounds__(256)
void gemm_bf16(const __nv_bfloat16* __restrict__ A, const __nv_bfloat16* __restrict__ W,
               const float* __restrict__ bias, const float* __restrict__ res,
               void* __restrict__ Cout, int Msz, int Nsz, int Ksz) {
    extern __shared__ char smem[];
    uint32_t sbase = smem_u32(smem);

    int tid = threadIdx.x;
    int wid = tid >> 5, lane = tid & 31;
    int m0 = blockIdx.y * 128, n0 = blockIdx.x * 256;
    int wm = (wid & 1) * 64, wn = (wid >> 1) * 64;
    int lrow = lane & 15;
    int lko  = (lane >> 4) * 16;

    const __nv_bfloat16* Aop = A;
    const __nv_bfloat16* Wop = W;
    const float* resp = res;
    float* CpF = (float*)Cout;
    __nv_bfloat16* CpH = (__nv_bfloat16*)Cout;
    if (EPI == 3) {
        size_t z = blockIdx.z;
        Wop  = W + z * (size_t)Ln * Cn;     // aggT batch slice [L, C] bf16
        resp = res + z * (size_t)Ln * Cn;   // xn f32 batch slice [L, C]
        CpF  = (float*)Cout + z * (size_t)Cn * Ln;
    }

    float acc[4][8][4];
    #pragma unroll
    for (int i = 0; i < 4; i++)
        #pragma unroll
        for (int j = 0; j < 8; j++)
            #pragma unroll
            for (int c = 0; c < 4; c++) acc[i][j][c] = 0.f;

    int arow = tid >> 2;          // 0..63
    int acol = tid & 3;           // 0..3 (16B chunks of 8 bf16)

    auto load_chunk = [&](int kt, int s) {
        uint32_t dA = sbase + s * STG;
        uint32_t dB = dA + STG_A;
        const __nv_bfloat16* ga = Aop + (size_t)(m0 + arow) * Ksz + kt * 32 + acol * 8;
        cp16(dA + (uint32_t)(arow * ROWB + acol * 16), ga);
        cp16(dA + (uint32_t)((arow + 64) * ROWB + acol * 16), ga + (size_t)64 * Ksz);
        const __nv_bfloat16* gb = Wop + (size_t)(n0 + arow) * Ksz + kt * 32 + acol * 8;
        #pragma unroll
        for (int i = 0; i < 4; i++)
            cp16(dB + (uint32_t)((arow + 64*i) * ROWB + acol * 16), gb + (size_t)(64*i) * Ksz);
        CP_COMMIT();
    };

    int nk = Ksz >> 5;
    load_chunk(0, 0);
    load_chunk(1, 1);
    load_chunk(2, 2);

    for (int kt = 0; kt < nk; kt++) {
        int s = kt & 3;
        CP_WAIT2();
        __syncthreads();
        // prefetch into slot freed last iteration (safe: all warps passed the
        // barrier above, which is after that slot's compute)
        if (kt + 3 < nk) load_chunk(kt + 3, (kt + 3) & 3);
        else CP_COMMIT();           // keep group count uniform for wait_group

        uint32_t sA = sbase + s * STG;
        uint32_t sB = sA + STG_A;
        #pragma unroll
        for (int ks = 0; ks < 2; ks++) {
            uint32_t af[4][4], bf[4][4];
            #pragma unroll
            for (int mt = 0; mt < 4; mt++)
                ldsm4(af[mt], sA + (uint32_t)((wm + mt*16 + lrow) * ROWB + ks*32 + lko));
            #pragma unroll
            for (int g = 0; g < 4; g++)
                ldsm4(bf[g], sB + (uint32_t)((wn + g*16 + lrow) * ROWB + ks*32 + lko));
            #pragma unroll
            for (int mt = 0; mt < 4; mt++)
                #pragma unroll
                for (int nt = 0; nt < 8; nt++) {
                    uint32_t bb[2] = { bf[nt>>1][nt&1], bf[nt>>1][(nt&1) + 2] };
                    mma_bf16(acc[mt][nt], af[mt], bb);
                }
        }
    }

    // -------- epilogue (direct STG from accumulators)
    int rm = lane >> 2, cn = (lane & 3) * 2;
    #pragma unroll
    for (int mt = 0; mt < 4; mt++) {
        int m = m0 + wm + mt*16 + rm;
        float bm0 = 0.f, bm1 = 0.f;
        if (EPI == 3) { bm0 = bias[m]; bm1 = bias[m + 8]; }
        #pragma unroll
        for (int nt = 0; nt < 8; nt++) {
            int n = n0 + wn + nt*8 + cn;
            float* c = acc[mt][nt];
            if (EPI == 0) {
                float2 bb = *(const float2*)&bias[n];
                *(float2*)&CpF[(size_t)m * Nsz + n]       = make_float2(c[0]+bb.x, c[1]+bb.y);
                *(float2*)&CpF[(size_t)(m+8) * Nsz + n]   = make_float2(c[2]+bb.x, c[3]+bb.y);
            } else if (EPI == 1) {
                float2 bb = *(const float2*)&bias[n];
                __nv_bfloat162 p0 = __floats2bfloat162_rn(gelu_exact(c[0]+bb.x), gelu_exact(c[1]+bb.y));
                __nv_bfloat162 p1 = __floats2bfloat162_rn(gelu_exact(c[2]+bb.x), gelu_exact(c[3]+bb.y));
                *(__nv_bfloat162*)&CpH[(size_t)m * Nsz + n]     = p0;
                *(__nv_bfloat162*)&CpH[(size_t)(m+8) * Nsz + n] = p1;
            } else if (EPI == 2) {
                float2 bb = *(const float2*)&bias[n];
                float2 r0 = *(const float2*)&resp[(size_t)m * Nsz + n];
                float2 r1 = *(const float2*)&resp[(size_t)(m+8) * Nsz + n];
                *(float2*)&CpF[(size_t)m * Nsz + n]     = make_float2(c[0]+bb.x+r0.x, c[1]+bb.y+r0.y);
                *(float2*)&CpF[(size_t)(m+8) * Nsz + n] = make_float2(c[2]+bb.x+r1.x, c[3]+bb.y+r1.y);
            } else {
                float x00 = resp[(size_t)n * Cn + m];
                float x01 = resp[(size_t)(n+1) * Cn + m];
                float x10 = resp[(size_t)n * Cn + m + 8];
                float x11 = resp[(size_t)(n+1) * Cn + m + 8];
                *(float2*)&CpF[(size_t)m * Ln + n]     = make_float2(c[0]+bm0+x00, c[1]+bm0+x01);
                *(float2*)&CpF[(size_t)(m+8) * Ln + n] = make_float2(c[2]+bm1+x10, c[3]+bm1+x11);
            }
        }
    }
}

// ---------------- f32 -> bf16 convert ----------------------------------------
__global__ void cvt_bf16_kernel(const float* __restrict__ in, __nv_bfloat16* __restrict__ out, int n) {
    int i = (blockIdx.x * blockDim.x + threadIdx.x) * 4;
    if (i < n) {
        float4 v = *(const float4*)(in + i);
        *(__nv_bfloat162*)(out + i)     = __floats2bfloat162_rn(v.x, v.y);
        *(__nv_bfloat162*)(out + i + 2) = __floats2bfloat162_rn(v.z, v.w);
    }
}

// ---------------- LayerNorm: bf16 out (+ optional f32 copy) ------------------
__global__ void ln_kernel(const float* __restrict__ in, const float* __restrict__ w,
                          const float* __restrict__ b, __nv_bfloat16* __restrict__ outb,
                          float* __restrict__ outf) {
    __shared__ float s8[8];
    int row = blockIdx.x, t = threadIdx.x;
    size_t base = (size_t)row * Cn;
    float v0 = in[base + t], v1 = in[base + t + 256];
    float mean = blockReduceSum256(v0 + v1, s8, t) * (1.0f / Cn);
    float d0 = v0 - mean, d1 = v1 - mean;
    float var = blockReduceSum256(d0*d0 + d1*d1, s8, t) * (1.0f / Cn);
    float rs = rsqrtf(var + 1e-5f);
    float o0 = d0 * rs * w[t]       + b[t];
    float o1 = d1 * rs * w[t + 256] + b[t + 256];
    outb[base + t]       = __float2bfloat16_rn(o0);
    outb[base + t + 256] = __float2bfloat16_rn(o1);
    if (outf) { outf[base + t] = o0; outf[base + t + 256] = o1; }
}

// x1 = attn_flat + x ; x1n = LN(x1) (bf16)
__global__ void x1_ln_kernel(const float* __restrict__ attn, const float* __restrict__ x,
                             const float* __restrict__ w, const float* __restrict__ b,
                             float* __restrict__ x1, __nv_bfloat16* __restrict__ x1nb) {
    __shared__ float s8[8];
    int row = blockIdx.x, t = threadIdx.x;
    size_t base = (size_t)row * Cn;
    float v0 = attn[base + t]       + x[base + t];
    float v1 = attn[base + t + 256] + x[base + t + 256];
    x1[base + t] = v0; x1[base + t + 256] = v1;
    float mean = blockReduceSum256(v0 + v1, s8, t) * (1.0f / Cn);
    float d0 = v0 - mean, d1 = v1 - mean;
    float var = blockReduceSum256(d0*d0 + d1*d1, s8, t) * (1.0f / Cn);
    float rs = rsqrtf(var + 1e-5f);
    x1nb[base + t]       = __float2bfloat16_rn(d0 * rs * w[t]       + b[t]);
    x1nb[base + t + 256] = __float2bfloat16_rn(d1 * rs * w[t + 256] + b[t + 256]);
}

// ---------------- k softmax over L (per (b, ck)) ----------------------------
__global__ void k_softmax(float* __restrict__ k) {
    __shared__ float red[32][8];
    int tx = threadIdx.x, ty = threadIdx.y;
    int ck = blockIdx.x * 8 + tx;
    int b  = blockIdx.y;
    size_t base = (size_t)b * Ln * Cn + ck;

    float m = -1e30f;
    for (int l = ty; l < Ln; l += 32) m = fmaxf(m, k[base + (size_t)l * Cn]);
    red[ty][tx] = m; __syncthreads();
    #pragma unroll
    for (int st = 16; st > 0; st >>= 1) {
        if (ty < st) red[ty][tx] = fmaxf(red[ty][tx], red[ty + st][tx]);
        __syncthreads();
    }
    m = red[0][tx]; __syncthreads();

    float s = 0.f;
    for (int l = ty; l < Ln; l += 32) s += __expf(k[base + (size_t)l * Cn] - m);
    red[ty][tx] = s; __syncthreads();
    #pragma unroll
    for (int st = 16; st > 0; st >>= 1) {
        if (ty < st) red[ty][tx] += red[ty + st][tx];
        __syncthreads();
    }
    s = red[0][tx]; __syncthreads();
    float inv = 1.0f / s;

    for (int l = ty; l < Ln; l += 32) {
        size_t idx = base + (size_t)l * Cn;
        k[idx] = __expf(k[idx] - m) * inv;
    }
}

// ---------------- q softmax over dk=64 --------------------------------------
__global__ void q_softmax(float* __restrict__ q) {
    int row = blockIdx.x;
    int w = threadIdx.x >> 5, lane = threadIdx.x & 31;
    size_t base = (size_t)row * Cn + w * DK;
    float a = q[base + lane], b = q[base + 32 + lane];
    float m = fmaxf(a, b);
    #pragma unroll
    for (int o = 16; o > 0; o >>= 1) m = fmaxf(m, __shfl_xor_sync(0xffffffffu, m, o));
    float e1 = __expf(a - m), e2 = __expf(b - m);
    float s = e1 + e2;
    #pragma unroll
    for (int o = 16; o > 0; o >>= 1) s += __shfl_xor_sync(0xffffffffu, s, o);
    float inv = 1.0f / s;
    q[base + lane]      = e1 * inv;
    q[base + 32 + lane] = e2 * inv;
}

__global__ void zero_kernel(float* __restrict__ p, int n) {
    int i = blockIdx.x * blockDim.x + threadIdx.x;
    if (i < n) p[i] = 0.f;
}

// ---------------- context[b,h,k,v] += sum_l ksm * val -----------------------
__global__ __launch_bounds__(256)
void context_kernel(const float* __restrict__ ksm, const float* __restrict__ val,
                    float* __restrict__ ctx) {
    __shared__ float sK[8][64];
    __shared__ float sV[8][64];
    int b = blockIdx.z, h = blockIdx.y;
    int l0 = blockIdx.x * (Ln / 16);
    int tid = threadIdx.x;
    int tx = tid & 15, ty = tid >> 4;
    int li = tid >> 5, cc = tid & 31;

    float acc[4][4] = {};
    for (int lc = l0; lc < l0 + Ln / 16; lc += 8) {
        size_t idx = ((size_t)(b * Ln + lc + li)) * Cn + h * DK + cc;
        sK[li][cc]      = ksm[idx];
        sK[li][cc + 32] = ksm[idx + 32];
        sV[li][cc]      = val[idx];
        sV[li][cc + 32] = val[idx + 32];
        __syncthreads();
        #pragma unroll
        for (int l = 0; l < 8; l++) {
            float kv[4], vv[4];
            #pragma unroll
            for (int i = 0; i < 4; i++) { kv[i] = sK[l][ty*4+i]; vv[i] = sV[l][tx*4+i]; }
            #pragma unroll
            for (int i = 0; i < 4; i++)
                #pragma unroll
                for (int j = 0; j < 4; j++) acc[i][j] = fmaf(kv[i], vv[j], acc[i][j]);
        }
        __syncthreads();
    }
    size_t cb = (size_t)(b * Hn + h) * DK * DK;
    #pragma unroll
    for (int i = 0; i < 4; i++)
        #pragma unroll
        for (int j = 0; j < 4; j++)
            atomicAdd(&ctx[cb + (size_t)(ty*4+i) * DK + tx*4+j], acc[i][j]);
}

// ---- aggT[b, l, h*64+v] = sum_k ctx[b,h,k,v] * qsm[b,l,h,k]  (bf16 out) ----
__global__ __launch_bounds__(256)
void agg_kernel(const float* __restrict__ qsm, const float* __restrict__ ctx,
                __nv_bfloat16* __restrict__ aggT) {
    __shared__ float sC[64][64];
    __shared__ float sQ[128][64];
    int b = blockIdx.z, h = blockIdx.y, l0 = blockIdx.x * 128;
    int tid = threadIdx.x;
    int tx = tid & 15, ty = tid >> 4;

    size_t cb = (size_t)(b * Hn + h) * DK * DK;
    for (int f = tid; f < 4096; f += 256) sC[f >> 6][f & 63] = ctx[cb + f];
    for (int f = tid; f < 8192; f += 256) {
        int l = f >> 6, kk = f & 63;
        sQ[l][kk] = qsm[((size_t)(b * Ln + l0 + l)) * Cn + h * DK + kk];
    }
    __syncthreads();

    float acc[4][8] = {};
    #pragma unroll
    for (int k = 0; k < 64; k++) {
        float cv[4], qv[8];
        #pragma unroll
        for (int i = 0; i < 4; i++) cv[i] = sC[k][tx*4+i];
        #pragma unroll
        for (int j = 0; j < 8; j++) qv[j] = sQ[ty*8+j][k];
        #pragma unroll
        for (int i = 0; i < 4; i++)
            #pragma unroll
            for (int j = 0; j < 8; j++) acc[i][j] = fmaf(cv[i], qv[j], acc[i][j]);
    }
    #pragma unroll
    for (int j = 0; j < 8; j++) {
        size_t ob = ((size_t)(b * Ln + l0 + ty*8 + j)) * Cn + h * DK + tx*4;
        *(__nv_bfloat162*)&aggT[ob]     = __floats2bfloat162_rn(acc[0][j], acc[1][j]);
        *(__nv_bfloat162*)&aggT[ob + 2] = __floats2bfloat162_rn(acc[2][j], acc[3][j]);
    }
}

// ---------------- host launcher ---------------------------------------------
extern "C" void kernel_launch(void* const* d_in, const int* in_sizes, int n_in,
                              void* d_out, int out_size) {
    (void)in_sizes; (void)n_in; (void)out_size;
    const float* x     = (const float*)d_in[0];
    const float* v     = (const float*)d_in[1];
    const float* ln1_w = (const float*)d_in[4];
    const float* ln1_b = (const float*)d_in[5];
    const float* lnv_w = (const float*)d_in[6];
    const float* lnv_b = (const float*)d_in[7];
    const float* ln2_w = (const float*)d_in[8];
    const float* ln2_b = (const float*)d_in[9];
    const float* wq    = (const float*)d_in[10];
    const float* bq    = (const float*)d_in[11];
    const float* wk    = (const float*)d_in[12];
    const float* bk    = (const float*)d_in[13];
    const float* wv    = (const float*)d_in[14];
    const float* bv    = (const float*)d_in[15];
    const float* wr    = (const float*)d_in[16];
    const float* br    = (const float*)d_in[17];
    const float* fc1_w = (const float*)d_in[18];
    const float* fc1_b = (const float*)d_in[19];
    const float* fc2_w = (const float*)d_in[20];
    const float* fc2_b = (const float*)d_in[21];
    float* out = (float*)d_out;

    float *p_xn, *p_q, *p_k, *p_val, *p_ctx, *p_attn, *p_x1;
    __nv_bfloat16 *p_xnb, *p_vnb, *p_aggT, *p_x1nb, *p_h1b;
    __nv_bfloat16 *p_wqb, *p_wkb, *p_wvb, *p_wrb, *p_f1b, *p_f2b;
    cudaGetSymbolAddress((void**)&p_xn,  g_xn);
    cudaGetSymbolAddress((void**)&p_xnb, g_xnb);
    cudaGetSymbolAddress((void**)&p_vnb, g_vnb);
    cudaGetSymbolAddress((void**)&p_q,   g_q);
    cudaGetSymbolAddress((void**)&p_k,   g_k);
    cudaGetSymbolAddress((void**)&p_val, g_val);
    cudaGetSymbolAddress((void**)&p_ctx, g_ctx);
    cudaGetSymbolAddress((void**)&p_aggT,g_aggT);
    cudaGetSymbolAddress((void**)&p_attn,g_attn);
    cudaGetSymbolAddress((void**)&p_x1,  g_x1);
    cudaGetSymbolAddress((void**)&p_x1nb,g_x1nb);
    cudaGetSymbolAddress((void**)&p_h1b, g_h1b);
    cudaGetSymbolAddress((void**)&p_wqb, g_wqb);
    cudaGetSymbolAddress((void**)&p_wkb, g_wkb);
    cudaGetSymbolAddress((void**)&p_wvb, g_wvb);
    cudaGetSymbolAddress((void**)&p_wrb, g_wrb);
    cudaGetSymbolAddress((void**)&p_f1b, g_f1b);
    cudaGetSymbolAddress((void**)&p_f2b, g_f2b);

    cudaFuncSetAttribute(gemm_bf16<0>, cudaFuncAttributeMaxDynamicSharedMemorySize, SMEM_REQ);
    cudaFuncSetAttribute(gemm_bf16<1>, cudaFuncAttributeMaxDynamicSharedMemorySize, SMEM_REQ);
    cudaFuncSetAttribute(gemm_bf16<2>, cudaFuncAttributeMaxDynamicSharedMemorySize, SMEM_REQ);
    cudaFuncSetAttribute(gemm_bf16<3>, cudaFuncAttributeMaxDynamicSharedMemorySize, SMEM_REQ);

    // 0) weight conversion (f32 -> bf16)
    cvt_bf16_kernel<<<(Cn*Cn/4 + 255)/256, 256>>>(wq, p_wqb, Cn*Cn);
    cvt_bf16_kernel<<<(Cn*Cn/4 + 255)/256, 256>>>(wk, p_wkb, Cn*Cn);
    cvt_bf16_kernel<<<(Cn*Cn/4 + 255)/256, 256>>>(wv, p_wvb, Cn*Cn);
    cvt_bf16_kernel<<<(Cn*Cn/4 + 255)/256, 256>>>(wr, p_wrb, Cn*Cn);
    cvt_bf16_kernel<<<(HID*Cn/4 + 255)/256, 256>>>(fc1_w, p_f1b, HID*Cn);
    cvt_bf16_kernel<<<(Cn*HID/4 + 255)/256, 256>>>(fc2_w, p_f2b, Cn*HID);

    // 1) LayerNorms
    ln_kernel<<<Mrows, 256>>>(x, ln1_w, ln1_b, p_xnb, p_xn);
    ln_kernel<<<Mrows, 256>>>(v, lnv_w, lnv_b, p_vnb, nullptr);

    // 2) q/k/val projections (bf16 mma, 128x256 tiles)
    dim3 gqkv(Cn / 256, Mrows / 128);
    gemm_bf16<0><<<gqkv, 256, SMEM_REQ>>>(p_xnb, p_wqb, bq, nullptr, p_q,   Mrows, Cn, Cn);
    gemm_bf16<0><<<gqkv, 256, SMEM_REQ>>>(p_vnb, p_wkb, bk, nullptr, p_k,   Mrows, Cn, Cn);
    gemm_bf16<0><<<gqkv, 256, SMEM_REQ>>>(p_vnb, p_wvb, bv, nullptr, p_val, Mrows, Cn, Cn);

    // 3) softmaxes
    k_softmax<<<dim3(Cn / 8, Bn), dim3(8, 32)>>>(p_k);
    q_softmax<<<Mrows, 256>>>(p_q);

    // 4) context = k_sm^T @ val
    zero_kernel<<<(Bn*Hn*DK*DK + 255) / 256, 256>>>(p_ctx, Bn*Hn*DK*DK);
    context_kernel<<<dim3(16, Hn, Bn), 256>>>(p_k, p_val, p_ctx);

    // 5) aggT = (ctx^T @ q_sm)^T  -> (B, L, C) bf16
    agg_kernel<<<dim3(Ln / 128, Hn, Bn), 256>>>(p_q, p_ctx, p_aggT);

    // 6) reproj: attn[z,c,l] = wr[c,:]·aggT[z,l,:] + br[c] + xn[z,l,c]
    gemm_bf16<3><<<dim3(Ln / 256, Cn / 128, Bn), 256, SMEM_REQ>>>(
        p_wrb, p_aggT, br, p_xn, p_attn, Cn, Ln, Cn);

    // 7) x1 = attn + x ; x1n = LN(x1)
    x1_ln_kernel<<<Mrows, 256>>>(p_attn, x, ln2_w, ln2_b, p_x1, p_x1nb);

    // 8) MLP
    gemm_bf16<1><<<dim3(HID / 256, Mrows / 128), 256, SMEM_REQ>>>(
        p_x1nb, p_f1b, fc1_b, nullptr, p_h1b, Mrows, HID, Cn);
    gemm_bf16<2><<<dim3(Cn / 256, Mrows / 128), 256, SMEM_REQ>>>(
        p_h1b, p_f2b, fc2_b, p_x1, out, Mrows, Cn, HID);
}

// round 6
// speedup vs baseline: 1.6044x; 1.6044x over previous
#include <cuda_runtime.h>
#include <cuda_bf16.h>
#include <math.h>
#include <stdint.h>

#define Bn   8
#define Ln   9216
#define Cn   512
#define Hn   8
#define DK   64
#define HID  2048
#define Mrows (Bn*Ln)          // 73728
#define CKV  1024              // fused k|v width

// ---------------- scratch (device globals: no runtime allocation) ----------
__device__ float          g_xn  [Mrows*Cn];   // fp32 xn (reproj epilogue addend)
__device__ __nv_bfloat16  g_xnb [Mrows*Cn];   // bf16 xn (GEMM A)
__device__ __nv_bfloat16  g_vnb [Mrows*Cn];   // bf16 vn (GEMM A)
__device__ float          g_q   [Mrows*Cn];   // raw q projections (softmax in agg)
__device__ float          g_kv  [Mrows*CKV];  // fused [k | val]
__device__ float          g_ctx [Bn*Hn*DK*DK];
__device__ __nv_bfloat16  g_aggT[Mrows*Cn];   // (B, L, C) bf16 (reproj B operand)
__device__ float          g_attn[Mrows*Cn];   // reproj + xn, flat == (M, C) reinterpret
__device__ float          g_x1  [Mrows*Cn];
__device__ __nv_bfloat16  g_x1nb[Mrows*Cn];   // bf16 LN2 out (fc1 A)
__device__ __nv_bfloat16  g_h1b [Mrows*HID];  // bf16 gelu(fc1) (fc2 A)
// bf16 weights
__device__ __nv_bfloat16  g_wqb  [Cn*Cn];
__device__ __nv_bfloat16  g_wkvb [CKV*Cn];    // [wk ; wv]
__device__ __nv_bfloat16  g_wrb  [Cn*Cn];
__device__ __nv_bfloat16  g_f1b  [HID*Cn];
__device__ __nv_bfloat16  g_f2b  [Cn*HID];
__device__ float          g_bkv  [CKV];       // [bk ; bv]

// ---------------- asm helpers ------------------------------------------------
__device__ __forceinline__ uint32_t smem_u32(const void* p) {
    uint32_t a;
    asm("{ .reg .u64 t; cvta.to.shared.u64 t, %1; cvt.u32.u64 %0, t; }" : "=r"(a) : "l"(p));
    return a;
}
__device__ __forceinline__ void ldsm4(uint32_t* r, uint32_t a) {
    asm volatile("ldmatrix.sync.aligned.m8n8.x4.shared.b16 {%0,%1,%2,%3}, [%4];"
        : "=r"(r[0]), "=r"(r[1]), "=r"(r[2]), "=r"(r[3]) : "r"(a));
}
__device__ __forceinline__ void mma_bf16(float* c, const uint32_t* a, const uint32_t* b) {
    asm volatile("mma.sync.aligned.m16n8k16.row.col.f32.bf16.bf16.f32 "
        "{%0,%1,%2,%3}, {%4,%5,%6,%7}, {%8,%9}, {%0,%1,%2,%3};"
        : "+f"(c[0]), "+f"(c[1]), "+f"(c[2]), "+f"(c[3])
        : "r"(a[0]), "r"(a[1]), "r"(a[2]), "r"(a[3]), "r"(b[0]), "r"(b[1]));
}
__device__ __forceinline__ void cp16(uint32_t dst, const void* src) {
    asm volatile("cp.async.cg.shared.global [%0], [%1], 16;" :: "r"(dst), "l"(src));
}
#define CP_COMMIT() asm volatile("cp.async.commit_group;" ::: "memory")
#define CP_WAIT2()  asm volatile("cp.async.wait_group 2;" ::: "memory")

// smem tile geometry: rows of 32 bf16 (64B) padded to 80B -> conflict-free LDSM
#define ROWB   80
#define STG_A  (128*ROWB)          // 10240
#define STG    (2*STG_A)           // 20480 per stage
#define NST    4
#define SMEM_REQ (NST*STG)         // 81920  (2 CTAs/SM)

// ---------------- misc device helpers ---------------------------------------
__device__ __forceinline__ float gelu_exact(float x) {
    return 0.5f * x * (1.0f + erff(x * 0.70710678118654752f));
}

__device__ __forceinline__ float blockReduceSum256(float v, float* s8, int tid) {
    #pragma unroll
    for (int o = 16; o > 0; o >>= 1) v += __shfl_xor_sync(0xffffffffu, v, o);
    int lane = tid & 31, w = tid >> 5;
    if (lane == 0) s8[w] = v;
    __syncthreads();
    if (w == 0) {
        v = (lane < 8) ? s8[lane] : 0.f;
        #pragma unroll
        for (int o = 4; o > 0; o >>= 1) v += __shfl_xor_sync(0xffffffffu, v, o);
        if (lane == 0) s8[0] = v;
    }
    __syncthreads();
    float r = s8[0];
    __syncthreads();
    return r;
}

// ---------------- bf16 GEMM (NT): C[M,N] = A[M,K]·W[N,K]^T + epilogue -------
// CTA 128x128, warp tile 64x32 (8 warps), K-chunk 32, 4-stage cp.async,
// single __syncthreads per chunk (prefetch kt+3 after the barrier).
// EPI: 0 bias(n) -> f32        1 bias(n)+gelu -> bf16
//      2 bias(n)+res -> f32    3 reproj: br(m) + xn gather, out stride Ln -> f32
template<int EPI>
__global__ __launch_bounds__(256)
void gemm_bf16(const __nv_bfloat16* __restrict__ A, const __nv_bfloat16* __restrict__ W,
               const float* __restrict__ bias, const float* __restrict__ res,
               void* __restrict__ Cout, int Msz, int Nsz, int Ksz) {
    extern __shared__ char smem[];
    uint32_t sbase = smem_u32(smem);

    int tid = threadIdx.x;
    int wid = tid >> 5, lane = tid & 31;
    int m0 = blockIdx.y * 128, n0 = blockIdx.x * 128;
    int wm = (wid & 1) * 64, wn = (wid >> 1) * 32;
    int lrow = lane & 15;
    int lko  = (lane >> 4) * 16;

    const __nv_bfloat16* Aop = A;
    const __nv_bfloat16* Wop = W;
    const float* resp = res;
    float* CpF = (float*)Cout;
    __nv_bfloat16* CpH = (__nv_bfloat16*)Cout;
    if (EPI == 3) {
        size_t z = blockIdx.z;
        Wop  = W + z * (size_t)Ln * Cn;     // aggT batch slice [L, C] bf16
        resp = res + z * (size_t)Ln * Cn;   // xn f32 batch slice [L, C]
        CpF  = (float*)Cout + z * (size_t)Cn * Ln;
    }

    float acc[4][4][4];
    #pragma unroll
    for (int i = 0; i < 4; i++)
        #pragma unroll
        for (int j = 0; j < 4; j++)
            #pragma unroll
            for (int c = 0; c < 4; c++) acc[i][j][c] = 0.f;

    int arow = tid >> 2;          // 0..63
    int acol = tid & 3;           // 0..3 (16B chunks of 8 bf16)

    auto load_chunk = [&](int kt, int s) {
        uint32_t dA = sbase + s * STG;
        uint32_t dB = dA + STG_A;
        const __nv_bfloat16* ga = Aop + (size_t)(m0 + arow) * Ksz + kt * 32 + acol * 8;
        cp16(dA + (uint32_t)(arow * ROWB + acol * 16), ga);
        cp16(dA + (uint32_t)((arow + 64) * ROWB + acol * 16), ga + (size_t)64 * Ksz);
        const __nv_bfloat16* gb = Wop + (size_t)(n0 + arow) * Ksz + kt * 32 + acol * 8;
        cp16(dB + (uint32_t)(arow * ROWB + acol * 16), gb);
        cp16(dB + (uint32_t)((arow + 64) * ROWB + acol * 16), gb + (size_t)64 * Ksz);
        CP_COMMIT();
    };

    int nk = Ksz >> 5;
    load_chunk(0, 0);
    load_chunk(1, 1);
    load_chunk(2, 2);

    for (int kt = 0; kt < nk; kt++) {
        int s = kt & 3;
        CP_WAIT2();
        __syncthreads();
        // prefetch into slot (kt+3)&3, freed by the compute of iteration kt-1
        // (all warps passed the barrier above after finishing it)
        if (kt + 3 < nk) load_chunk(kt + 3, (kt + 3) & 3);
        else CP_COMMIT();           // keep group count uniform for wait_group

        uint32_t sA = sbase + s * STG;
        uint32_t sB = sA + STG_A;
        #pragma unroll
        for (int ks = 0; ks < 2; ks++) {
            uint32_t af[4][4], bf[2][4];
            #pragma unroll
            for (int mt = 0; mt < 4; mt++)
                ldsm4(af[mt], sA + (uint32_t)((wm + mt*16 + lrow) * ROWB + ks*32 + lko));
            #pragma unroll
            for (int g = 0; g < 2; g++)
                ldsm4(bf[g], sB + (uint32_t)((wn + g*16 + lrow) * ROWB + ks*32 + lko));
            #pragma unroll
            for (int mt = 0; mt < 4; mt++)
                #pragma unroll
                for (int nt = 0; nt < 4; nt++) {
                    uint32_t bb[2] = { bf[nt>>1][nt&1], bf[nt>>1][(nt&1) + 2] };
                    mma_bf16(acc[mt][nt], af[mt], bb);
                }
        }
    }

    // -------- epilogue (direct STG from accumulators)
    int rm = lane >> 2, cn = (lane & 3) * 2;
    #pragma unroll
    for (int mt = 0; mt < 4; mt++) {
        int m = m0 + wm + mt*16 + rm;
        float bm0 = 0.f, bm1 = 0.f;
        if (EPI == 3) { bm0 = bias[m]; bm1 = bias[m + 8]; }
        #pragma unroll
        for (int nt = 0; nt < 4; nt++) {
            int n = n0 + wn + nt*8 + cn;
            float* c = acc[mt][nt];
            if (EPI == 0) {
                float2 bb = *(const float2*)&bias[n];
                *(float2*)&CpF[(size_t)m * Nsz + n]       = make_float2(c[0]+bb.x, c[1]+bb.y);
                *(float2*)&CpF[(size_t)(m+8) * Nsz + n]   = make_float2(c[2]+bb.x, c[3]+bb.y);
            } else if (EPI == 1) {
                float2 bb = *(const float2*)&bias[n];
                __nv_bfloat162 p0 = __floats2bfloat162_rn(gelu_exact(c[0]+bb.x), gelu_exact(c[1]+bb.y));
                __nv_bfloat162 p1 = __floats2bfloat162_rn(gelu_exact(c[2]+bb.x), gelu_exact(c[3]+bb.y));
                *(__nv_bfloat162*)&CpH[(size_t)m * Nsz + n]     = p0;
                *(__nv_bfloat162*)&CpH[(size_t)(m+8) * Nsz + n] = p1;
            } else if (EPI == 2) {
                float2 bb = *(const float2*)&bias[n];
                float2 r0 = *(const float2*)&resp[(size_t)m * Nsz + n];
                float2 r1 = *(const float2*)&resp[(size_t)(m+8) * Nsz + n];
                *(float2*)&CpF[(size_t)m * Nsz + n]     = make_float2(c[0]+bb.x+r0.x, c[1]+bb.y+r0.y);
                *(float2*)&CpF[(size_t)(m+8) * Nsz + n] = make_float2(c[2]+bb.x+r1.x, c[3]+bb.y+r1.y);
            } else {
                float x00 = resp[(size_t)n * Cn + m];
                float x01 = resp[(size_t)(n+1) * Cn + m];
                float x10 = resp[(size_t)n * Cn + m + 8];
                float x11 = resp[(size_t)(n+1) * Cn + m + 8];
                *(float2*)&CpF[(size_t)m * Ln + n]     = make_float2(c[0]+bm0+x00, c[1]+bm0+x01);
                *(float2*)&CpF[(size_t)(m+8) * Ln + n] = make_float2(c[2]+bm1+x10, c[3]+bm1+x11);
            }
        }
    }
}

// ---------------- f32 -> bf16 convert ----------------------------------------
__global__ void cvt_bf16_kernel(const float* __restrict__ in, __nv_bfloat16* __restrict__ out, int n) {
    int i = (blockIdx.x * blockDim.x + threadIdx.x) * 4;
    if (i < n) {
        float4 v = *(const float4*)(in + i);
        *(__nv_bfloat162*)(out + i)     = __floats2bfloat162_rn(v.x, v.y);
        *(__nv_bfloat162*)(out + i + 2) = __floats2bfloat162_rn(v.z, v.w);
    }
}

// concat [a(512) ; b(512)] -> o(1024)
__global__ void concat_bias_kernel(const float* __restrict__ a, const float* __restrict__ b,
                                   float* __restrict__ o) {
    int i = blockIdx.x * 256 + threadIdx.x;
    o[i] = (i < Cn) ? a[i] : b[i - Cn];
}

// ---------------- LayerNorm: bf16 out (+ optional f32 copy) ------------------
__global__ void ln_kernel(const float* __restrict__ in, const float* __restrict__ w,
                          const float* __restrict__ b, __nv_bfloat16* __restrict__ outb,
                          float* __restrict__ outf) {
    __shared__ float s8[8];
    int row = blockIdx.x, t = threadIdx.x;
    size_t base = (size_t)row * Cn;
    float v0 = in[base + t], v1 = in[base + t + 256];
    float mean = blockReduceSum256(v0 + v1, s8, t) * (1.0f / Cn);
    float d0 = v0 - mean, d1 = v1 - mean;
    float var = blockReduceSum256(d0*d0 + d1*d1, s8, t) * (1.0f / Cn);
    float rs = rsqrtf(var + 1e-5f);
    float o0 = d0 * rs * w[t]       + b[t];
    float o1 = d1 * rs * w[t + 256] + b[t + 256];
    outb[base + t]       = __float2bfloat16_rn(o0);
    outb[base + t + 256] = __float2bfloat16_rn(o1);
    if (outf) { outf[base + t] = o0; outf[base + t + 256] = o1; }
}

// x1 = attn_flat + x ; x1n = LN(x1) (bf16)
__global__ void x1_ln_kernel(const float* __restrict__ attn, const float* __restrict__ x,
                             const float* __restrict__ w, const float* __restrict__ b,
                             float* __restrict__ x1, __nv_bfloat16* __restrict__ x1nb) {
    __shared__ float s8[8];
    int row = blockIdx.x, t = threadIdx.x;
    size_t base = (size_t)row * Cn;
    float v0 = attn[base + t]       + x[base + t];
    float v1 = attn[base + t + 256] + x[base + t + 256];
    x1[base + t] = v0; x1[base + t + 256] = v1;
    float mean = blockReduceSum256(v0 + v1, s8, t) * (1.0f / Cn);
    float d0 = v0 - mean, d1 = v1 - mean;
    float var = blockReduceSum256(d0*d0 + d1*d1, s8, t) * (1.0f / Cn);
    float rs = rsqrtf(var + 1e-5f);
    x1nb[base + t]       = __float2bfloat16_rn(d0 * rs * w[t]       + b[t]);
    x1nb[base + t + 256] = __float2bfloat16_rn(d1 * rs * w[t + 256] + b[t + 256]);
}

// ---------------- k softmax over L (per (b, ck)), strided buffer ------------
__global__ void k_softmax(float* __restrict__ kv) {
    __shared__ float red[32][8];
    int tx = threadIdx.x, ty = threadIdx.y;
    int ck = blockIdx.x * 8 + tx;
    int b  = blockIdx.y;
    size_t base = (size_t)b * Ln * CKV + ck;

    float m = -1e30f;
    for (int l = ty; l < Ln; l += 32) m = fmaxf(m, kv[base + (size_t)l * CKV]);
    red[ty][tx] = m; __syncthreads();
    #pragma unroll
    for (int st = 16; st > 0; st >>= 1) {
        if (ty < st) red[ty][tx] = fmaxf(red[ty][tx], red[ty + st][tx]);
        __syncthreads();
    }
    m = red[0][tx]; __syncthreads();

    float s = 0.f;
    for (int l = ty; l < Ln; l += 32) s += __expf(kv[base + (size_t)l * CKV] - m);
    red[ty][tx] = s; __syncthreads();
    #pragma unroll
    for (int st = 16; st > 0; st >>= 1) {
        if (ty < st) red[ty][tx] += red[ty + st][tx];
        __syncthreads();
    }
    s = red[0][tx]; __syncthreads();
    float inv = 1.0f / s;

    for (int l = ty; l < Ln; l += 32) {
        size_t idx = base + (size_t)l * CKV;
        kv[idx] = __expf(kv[idx] - m) * inv;
    }
}

__global__ void zero_kernel(float* __restrict__ p, int n) {
    int i = blockIdx.x * blockDim.x + threadIdx.x;
    if (i < n) p[i] = 0.f;
}

// ---------------- context[b,h,k,v] += sum_l ksm * val (fused kv buffer) -----
__global__ __launch_bounds__(256)
void context_kernel(const float* __restrict__ kv, float* __restrict__ ctx) {
    __shared__ float sK[8][64];
    __shared__ float sV[8][64];
    int b = blockIdx.z, h = blockIdx.y;
    int l0 = blockIdx.x * (Ln / 16);
    int tid = threadIdx.x;
    int tx = tid & 15, ty = tid >> 4;
    int li = tid >> 5, cc = tid & 31;

    float acc[4][4] = {};
    for (int lc = l0; lc < l0 + Ln / 16; lc += 8) {
        size_t idx = ((size_t)(b * Ln + lc + li)) * CKV + h * DK + cc;
        sK[li][cc]      = kv[idx];
        sK[li][cc + 32] = kv[idx + 32];
        sV[li][cc]      = kv[idx + Cn];
        sV[li][cc + 32] = kv[idx + Cn + 32];
        __syncthreads();
        #pragma unroll
        for (int l = 0; l < 8; l++) {
            float kvv[4], vv[4];
            #pragma unroll
            for (int i = 0; i < 4; i++) { kvv[i] = sK[l][ty*4+i]; vv[i] = sV[l][tx*4+i]; }
            #pragma unroll
            for (int i = 0; i < 4; i++)
                #pragma unroll
                for (int j = 0; j < 4; j++) acc[i][j] = fmaf(kvv[i], vv[j], acc[i][j]);
        }
        __syncthreads();
    }
    size_t cb = (size_t)(b * Hn + h) * DK * DK;
    #pragma unroll
    for (int i = 0; i < 4; i++)
        #pragma unroll
        for (int j = 0; j < 4; j++)
            atomicAdd(&ctx[cb + (size_t)(ty*4+i) * DK + tx*4+j], acc[i][j]);
}

// ---- aggT[b, l, h*64+v] = sum_k ctx[b,h,k,v] * softmax_k(q[b,l,h,:]) -------
// q softmax (over dk=64) computed in-block; bf16 out.
__global__ __launch_bounds__(256)
void agg_kernel(const float* __restrict__ qraw, const float* __restrict__ ctx,
                __nv_bfloat16* __restrict__ aggT) {
    __shared__ float sC[64][64];
    __shared__ float sQ[128][65];   // padded: conflict-free row access
    int b = blockIdx.z, h = blockIdx.y, l0 = blockIdx.x * 128;
    int tid = threadIdx.x;
    int tx = tid & 15, ty = tid >> 4;

    size_t cb = (size_t)(b * Hn + h) * DK * DK;
    for (int f = tid; f < 4096; f += 256) sC[f >> 6][f & 63] = ctx[cb + f];
    for (int f = tid; f < 8192; f += 256) {
        int l = f >> 6, kk = f & 63;
        sQ[l][kk] = qraw[((size_t)(b * Ln + l0 + l)) * Cn + h * DK + kk];
    }
    __syncthreads();

    // in-block q softmax over the 64 channels of this head (2 threads/row)
    {
        int r = tid >> 1;
        int off = (tid & 1) * 32;
        float m = -1e30f;
        #pragma unroll
        for (int j = 0; j < 32; j++) m = fmaxf(m, sQ[r][off + j]);
        m = fmaxf(m, __shfl_xor_sync(0xffffffffu, m, 1));
        float s = 0.f;
        #pragma unroll
        for (int j = 0; j < 32; j++) {
            float e = __expf(sQ[r][off + j] - m);
            sQ[r][off + j] = e;
            s += e;
        }
        s += __shfl_xor_sync(0xffffffffu, s, 1);
        float inv = 1.0f / s;
        #pragma unroll
        for (int j = 0; j < 32; j++) sQ[r][off + j] *= inv;
    }
    __syncthreads();

    float acc[4][8] = {};
    #pragma unroll
    for (int k = 0; k < 64; k++) {
        float cv[4], qv[8];
        #pragma unroll
        for (int i = 0; i < 4; i++) cv[i] = sC[k][tx*4+i];
        #pragma unroll
        for (int j = 0; j < 8; j++) qv[j] = sQ[ty*8+j][k];
        #pragma unroll
        for (int i = 0; i < 4; i++)
            #pragma unroll
            for (int j = 0; j < 8; j++) acc[i][j] = fmaf(cv[i], qv[j], acc[i][j]);
    }
    #pragma unroll
    for (int j = 0; j < 8; j++) {
        size_t ob = ((size_t)(b * Ln + l0 + ty*8 + j)) * Cn + h * DK + tx*4;
        *(__nv_bfloat162*)&aggT[ob]     = __floats2bfloat162_rn(acc[0][j], acc[1][j]);
        *(__nv_bfloat162*)&aggT[ob + 2] = __floats2bfloat162_rn(acc[2][j], acc[3][j]);
    }
}

// ---------------- host launcher ---------------------------------------------
extern "C" void kernel_launch(void* const* d_in, const int* in_sizes, int n_in,
                              void* d_out, int out_size) {
    (void)in_sizes; (void)n_in; (void)out_size;
    const float* x     = (const float*)d_in[0];
    const float* v     = (const float*)d_in[1];
    const float* ln1_w = (const float*)d_in[4];
    const float* ln1_b = (const float*)d_in[5];
    const float* lnv_w = (const float*)d_in[6];
    const float* lnv_b = (const float*)d_in[7];
    const float* ln2_w = (const float*)d_in[8];
    const float* ln2_b = (const float*)d_in[9];
    const float* wq    = (const float*)d_in[10];
    const float* bq    = (const float*)d_in[11];
    const float* wk    = (const float*)d_in[12];
    const float* bk    = (const float*)d_in[13];
    const float* wv    = (const float*)d_in[14];
    const float* bv    = (const float*)d_in[15];
    const float* wr    = (const float*)d_in[16];
    const float* br    = (const float*)d_in[17];
    const float* fc1_w = (const float*)d_in[18];
    const float* fc1_b = (const float*)d_in[19];
    const float* fc2_w = (const float*)d_in[20];
    const float* fc2_b = (const float*)d_in[21];
    float* out = (float*)d_out;

    float *p_xn, *p_q, *p_kv, *p_ctx, *p_attn, *p_x1, *p_bkv;
    __nv_bfloat16 *p_xnb, *p_vnb, *p_aggT, *p_x1nb, *p_h1b;
    __nv_bfloat16 *p_wqb, *p_wkvb, *p_wrb, *p_f1b, *p_f2b;
    cudaGetSymbolAddress((void**)&p_xn,  g_xn);
    cudaGetSymbolAddress((void**)&p_xnb, g_xnb);
    cudaGetSymbolAddress((void**)&p_vnb, g_vnb);
    cudaGetSymbolAddress((void**)&p_q,   g_q);
    cudaGetSymbolAddress((void**)&p_kv,  g_kv);
    cudaGetSymbolAddress((void**)&p_ctx, g_ctx);
    cudaGetSymbolAddress((void**)&p_aggT,g_aggT);
    cudaGetSymbolAddress((void**)&p_attn,g_attn);
    cudaGetSymbolAddress((void**)&p_x1,  g_x1);
    cudaGetSymbolAddress((void**)&p_x1nb,g_x1nb);
    cudaGetSymbolAddress((void**)&p_h1b, g_h1b);
    cudaGetSymbolAddress((void**)&p_wqb, g_wqb);
    cudaGetSymbolAddress((void**)&p_wkvb,g_wkvb);
    cudaGetSymbolAddress((void**)&p_wrb, g_wrb);
    cudaGetSymbolAddress((void**)&p_f1b, g_f1b);
    cudaGetSymbolAddress((void**)&p_f2b, g_f2b);
    cudaGetSymbolAddress((void**)&p_bkv, g_bkv);

    cudaFuncSetAttribute(gemm_bf16<0>, cudaFuncAttributeMaxDynamicSharedMemorySize, SMEM_REQ);
    cudaFuncSetAttribute(gemm_bf16<1>, cudaFuncAttributeMaxDynamicSharedMemorySize, SMEM_REQ);
    cudaFuncSetAttribute(gemm_bf16<2>, cudaFuncAttributeMaxDynamicSharedMemorySize, SMEM_REQ);
    cudaFuncSetAttribute(gemm_bf16<3>, cudaFuncAttributeMaxDynamicSharedMemorySize, SMEM_REQ);

    // 0) weight conversion (f32 -> bf16); wk,wv concatenated
    cvt_bf16_kernel<<<(Cn*Cn/4 + 255)/256, 256>>>(wq, p_wqb, Cn*Cn);
    cvt_bf16_kernel<<<(Cn*Cn/4 + 255)/256, 256>>>(wk, p_wkvb, Cn*Cn);
    cvt_bf16_kernel<<<(Cn*Cn/4 + 255)/256, 256>>>(wv, p_wkvb + (size_t)Cn*Cn, Cn*Cn);
    cvt_bf16_kernel<<<(Cn*Cn/4 + 255)/256, 256>>>(wr, p_wrb, Cn*Cn);
    cvt_bf16_kernel<<<(HID*Cn/4 + 255)/256, 256>>>(fc1_w, p_f1b, HID*Cn);
    cvt_bf16_kernel<<<(Cn*HID/4 + 255)/256, 256>>>(fc2_w, p_f2b, Cn*HID);
    concat_bias_kernel<<<CKV/256, 256>>>(bk, bv, p_bkv);

    // 1) LayerNorms
    ln_kernel<<<Mrows, 256>>>(x, ln1_w, ln1_b, p_xnb, p_xn);
    ln_kernel<<<Mrows, 256>>>(v, lnv_w, lnv_b, p_vnb, nullptr);

    // 2) projections: q (N=512), fused k|v (N=1024)
    gemm_bf16<0><<<dim3(Cn / 128, Mrows / 128), 256, SMEM_REQ>>>(
        p_xnb, p_wqb, bq, nullptr, p_q, Mrows, Cn, Cn);
    gemm_bf16<0><<<dim3(CKV / 128, Mrows / 128), 256, SMEM_REQ>>>(
        p_vnb, p_wkvb, p_bkv, nullptr, p_kv, Mrows, CKV, Cn);

    // 3) k softmax (over L) on fused buffer; q softmax folded into agg
    k_softmax<<<dim3(Cn / 8, Bn), dim3(8, 32)>>>(p_kv);

    // 4) context = k_sm^T @ val
    zero_kernel<<<(Bn*Hn*DK*DK + 255) / 256, 256>>>(p_ctx, Bn*Hn*DK*DK);
    context_kernel<<<dim3(16, Hn, Bn), 256>>>(p_kv, p_ctx);

    // 5) aggT = (ctx^T @ softmax(q))^T  -> (B, L, C) bf16
    agg_kernel<<<dim3(Ln / 128, Hn, Bn), 256>>>(p_q, p_ctx, p_aggT);

    // 6) reproj: attn[z,c,l] = wr[c,:]·aggT[z,l,:] + br[c] + xn[z,l,c]
    gemm_bf16<3><<<dim3(Ln / 128, Cn / 128, Bn), 256, SMEM_REQ>>>(
        p_wrb, p_aggT, br, p_xn, p_attn, Cn, Ln, Cn);

    // 7) x1 = attn + x ; x1n = LN(x1)
    x1_ln_kernel<<<Mrows, 256>>>(p_attn, x, ln2_w, ln2_b, p_x1, p_x1nb);

    // 8) MLP
    gemm_bf16<1><<<dim3(HID / 128, Mrows / 128), 256, SMEM_REQ>>>(
        p_x1nb, p_f1b, fc1_b, nullptr, p_h1b, Mrows, HID, Cn);
    gemm_bf16<2><<<dim3(Cn / 128, Mrows / 128), 256, SMEM_REQ>>>(
        p_h1b, p_f2b, fc2_b, p_x1, out, Mrows, Cn, HID);
}

// round 7
// speedup vs baseline: 1.6343x; 1.0186x over previous
#include <cuda_runtime.h>
#include <cuda_bf16.h>
#include <math.h>
#include <stdint.h>

#define Bn   8
#define Ln   9216
#define Cn   512
#define Hn   8
#define DK   64
#define HID  2048
#define Mrows (Bn*Ln)          // 73728
#define CKV  1024              // fused k|v width

// ---------------- scratch (device globals: no runtime allocation) ----------
__device__ float          g_xn  [Mrows*Cn];   // fp32 xn (transpose source)
__device__ float          g_xnT [Mrows*Cn];   // fp32 xn transposed (B,C,L)
__device__ __nv_bfloat16  g_xnb [Mrows*Cn];   // bf16 xn (GEMM A)
__device__ __nv_bfloat16  g_vnb [Mrows*Cn];   // bf16 vn (GEMM A)
__device__ __nv_bfloat16  g_qb  [Mrows*Cn];   // bf16 raw q
__device__ __nv_bfloat16  g_kvb [Mrows*CKV];  // bf16 fused [k | val] (raw)
__device__ float          g_kmax[Bn*Cn];
__device__ float          g_kinv[Bn*Cn];
__device__ float          g_ctx [Bn*Hn*DK*DK];
__device__ __nv_bfloat16  g_aggT[Mrows*Cn];   // (B, L, C) bf16 (reproj B operand)
__device__ float          g_attn[Mrows*Cn];   // reproj + br, flat == (M, C) reinterpret
__device__ float          g_x1  [Mrows*Cn];
__device__ __nv_bfloat16  g_x1nb[Mrows*Cn];   // bf16 LN2 out (fc1 A)
__device__ __nv_bfloat16  g_h1b [Mrows*HID];  // bf16 gelu(fc1) (fc2 A)
// bf16 weights
__device__ __nv_bfloat16  g_wqb  [Cn*Cn];
__device__ __nv_bfloat16  g_wkvb [CKV*Cn];    // [wk ; wv]
__device__ __nv_bfloat16  g_wrb  [Cn*Cn];
__device__ __nv_bfloat16  g_f1b  [HID*Cn];
__device__ __nv_bfloat16  g_f2b  [Cn*HID];
__device__ float          g_bkv  [CKV];       // [bk ; bv]

// ---------------- asm helpers ------------------------------------------------
__device__ __forceinline__ uint32_t smem_u32(const void* p) {
    uint32_t a;
    asm("{ .reg .u64 t; cvta.to.shared.u64 t, %1; cvt.u32.u64 %0, t; }" : "=r"(a) : "l"(p));
    return a;
}
__device__ __forceinline__ void ldsm4(uint32_t* r, uint32_t a) {
    asm volatile("ldmatrix.sync.aligned.m8n8.x4.shared.b16 {%0,%1,%2,%3}, [%4];"
        : "=r"(r[0]), "=r"(r[1]), "=r"(r[2]), "=r"(r[3]) : "r"(a));
}
__device__ __forceinline__ void mma_bf16(float* c, const uint32_t* a, const uint32_t* b) {
    asm volatile("mma.sync.aligned.m16n8k16.row.col.f32.bf16.bf16.f32 "
        "{%0,%1,%2,%3}, {%4,%5,%6,%7}, {%8,%9}, {%0,%1,%2,%3};"
        : "+f"(c[0]), "+f"(c[1]), "+f"(c[2]), "+f"(c[3])
        : "r"(a[0]), "r"(a[1]), "r"(a[2]), "r"(a[3]), "r"(b[0]), "r"(b[1]));
}
__device__ __forceinline__ void cp16(uint32_t dst, const void* src) {
    asm volatile("cp.async.cg.shared.global [%0], [%1], 16;" :: "r"(dst), "l"(src));
}
#define CP_COMMIT() asm volatile("cp.async.commit_group;" ::: "memory")
#define CP_WAIT2()  asm volatile("cp.async.wait_group 2;" ::: "memory")

// smem tile geometry: rows of 32 bf16 (64B) padded to 80B -> conflict-free LDSM
#define ROWB   80
#define STG_A  (128*ROWB)          // 10240
#define STG    (2*STG_A)           // 20480 per stage
#define NST    4
#define SMEM_REQ (NST*STG)         // 81920  (2 CTAs/SM)

// ---------------- misc device helpers ---------------------------------------
__device__ __forceinline__ float gelu_exact(float x) {
    return 0.5f * x * (1.0f + erff(x * 0.70710678118654752f));
}

__device__ __forceinline__ float blockReduceSum256(float v, float* s8, int tid) {
    #pragma unroll
    for (int o = 16; o > 0; o >>= 1) v += __shfl_xor_sync(0xffffffffu, v, o);
    int lane = tid & 31, w = tid >> 5;
    if (lane == 0) s8[w] = v;
    __syncthreads();
    if (w == 0) {
        v = (lane < 8) ? s8[lane] : 0.f;
        #pragma unroll
        for (int o = 4; o > 0; o >>= 1) v += __shfl_xor_sync(0xffffffffu, v, o);
        if (lane == 0) s8[0] = v;
    }
    __syncthreads();
    float r = s8[0];
    __syncthreads();
    return r;
}

// ---------------- bf16 GEMM (NT): C[M,N] = A[M,K]·W[N,K]^T + epilogue -------
// CTA 128x128, warp tile 64x32 (8 warps), K-chunk 32, 4-stage cp.async,
// single __syncthreads per chunk (prefetch kt+3 after the barrier).
// EPI: 1 bias(n)+gelu -> bf16    2 bias(n)+res -> f32
//      4 bias(n) -> bf16         5 reproj: bias(m), out f32 stride Ln, batch z
template<int EPI>
__global__ __launch_bounds__(256)
void gemm_bf16(const __nv_bfloat16* __restrict__ A, const __nv_bfloat16* __restrict__ W,
               const float* __restrict__ bias, const float* __restrict__ res,
               void* __restrict__ Cout, int Msz, int Nsz, int Ksz) {
    extern __shared__ char smem[];
    uint32_t sbase = smem_u32(smem);

    int tid = threadIdx.x;
    int wid = tid >> 5, lane = tid & 31;
    int m0 = blockIdx.y * 128, n0 = blockIdx.x * 128;
    int wm = (wid & 1) * 64, wn = (wid >> 1) * 32;
    int lrow = lane & 15;
    int lko  = (lane >> 4) * 16;

    const __nv_bfloat16* Aop = A;
    const __nv_bfloat16* Wop = W;
    const float* resp = res;
    float* CpF = (float*)Cout;
    __nv_bfloat16* CpH = (__nv_bfloat16*)Cout;
    if (EPI == 5) {
        size_t z = blockIdx.z;
        Wop  = W + z * (size_t)Ln * Cn;     // aggT batch slice [L, C] bf16
        CpF  = (float*)Cout + z * (size_t)Cn * Ln;
    }

    float acc[4][4][4];
    #pragma unroll
    for (int i = 0; i < 4; i++)
        #pragma unroll
        for (int j = 0; j < 4; j++)
            #pragma unroll
            for (int c = 0; c < 4; c++) acc[i][j][c] = 0.f;

    int arow = tid >> 2;          // 0..63
    int acol = tid & 3;           // 0..3 (16B chunks of 8 bf16)

    auto load_chunk = [&](int kt, int s) {
        uint32_t dA = sbase + s * STG;
        uint32_t dB = dA + STG_A;
        const __nv_bfloat16* ga = Aop + (size_t)(m0 + arow) * Ksz + kt * 32 + acol * 8;
        cp16(dA + (uint32_t)(arow * ROWB + acol * 16), ga);
        cp16(dA + (uint32_t)((arow + 64) * ROWB + acol * 16), ga + (size_t)64 * Ksz);
        const __nv_bfloat16* gb = Wop + (size_t)(n0 + arow) * Ksz + kt * 32 + acol * 8;
        cp16(dB + (uint32_t)(arow * ROWB + acol * 16), gb);
        cp16(dB + (uint32_t)((arow + 64) * ROWB + acol * 16), gb + (size_t)64 * Ksz);
        CP_COMMIT();
    };

    int nk = Ksz >> 5;
    load_chunk(0, 0);
    load_chunk(1, 1);
    load_chunk(2, 2);

    for (int kt = 0; kt < nk; kt++) {
        int s = kt & 3;
        CP_WAIT2();
        __syncthreads();
        // prefetch into slot (kt+3)&3, freed by the compute of iteration kt-1
        if (kt + 3 < nk) load_chunk(kt + 3, (kt + 3) & 3);
        else CP_COMMIT();           // keep group count uniform for wait_group

        uint32_t sA = sbase + s * STG;
        uint32_t sB = sA + STG_A;
        #pragma unroll
        for (int ks = 0; ks < 2; ks++) {
            uint32_t af[4][4], bf[2][4];
            #pragma unroll
            for (int mt = 0; mt < 4; mt++)
                ldsm4(af[mt], sA + (uint32_t)((wm + mt*16 + lrow) * ROWB + ks*32 + lko));
            #pragma unroll
            for (int g = 0; g < 2; g++)
                ldsm4(bf[g], sB + (uint32_t)((wn + g*16 + lrow) * ROWB + ks*32 + lko));
            #pragma unroll
            for (int mt = 0; mt < 4; mt++)
                #pragma unroll
                for (int nt = 0; nt < 4; nt++) {
                    uint32_t bb[2] = { bf[nt>>1][nt&1], bf[nt>>1][(nt&1) + 2] };
                    mma_bf16(acc[mt][nt], af[mt], bb);
                }
        }
    }

    // -------- epilogue (direct STG from accumulators)
    int rm = lane >> 2, cn = (lane & 3) * 2;
    #pragma unroll
    for (int mt = 0; mt < 4; mt++) {
        int m = m0 + wm + mt*16 + rm;
        float bm0 = 0.f, bm1 = 0.f;
        if (EPI == 5) { bm0 = bias[m]; bm1 = bias[m + 8]; }
        #pragma unroll
        for (int nt = 0; nt < 4; nt++) {
            int n = n0 + wn + nt*8 + cn;
            float* c = acc[mt][nt];
            if (EPI == 1) {
                float2 bb = *(const float2*)&bias[n];
                __nv_bfloat162 p0 = __floats2bfloat162_rn(gelu_exact(c[0]+bb.x), gelu_exact(c[1]+bb.y));
                __nv_bfloat162 p1 = __floats2bfloat162_rn(gelu_exact(c[2]+bb.x), gelu_exact(c[3]+bb.y));
                *(__nv_bfloat162*)&CpH[(size_t)m * Nsz + n]     = p0;
                *(__nv_bfloat162*)&CpH[(size_t)(m+8) * Nsz + n] = p1;
            } else if (EPI == 2) {
                float2 bb = *(const float2*)&bias[n];
                float2 r0 = *(const float2*)&resp[(size_t)m * Nsz + n];
                float2 r1 = *(const float2*)&resp[(size_t)(m+8) * Nsz + n];
                *(float2*)&CpF[(size_t)m * Nsz + n]     = make_float2(c[0]+bb.x+r0.x, c[1]+bb.y+r0.y);
                *(float2*)&CpF[(size_t)(m+8) * Nsz + n] = make_float2(c[2]+bb.x+r1.x, c[3]+bb.y+r1.y);
            } else if (EPI == 4) {
                float2 bb = *(const float2*)&bias[n];
                __nv_bfloat162 p0 = __floats2bfloat162_rn(c[0]+bb.x, c[1]+bb.y);
                __nv_bfloat162 p1 = __floats2bfloat162_rn(c[2]+bb.x, c[3]+bb.y);
                *(__nv_bfloat162*)&CpH[(size_t)m * Nsz + n]     = p0;
                *(__nv_bfloat162*)&CpH[(size_t)(m+8) * Nsz + n] = p1;
            } else {  // EPI == 5
                *(float2*)&CpF[(size_t)m * Ln + n]     = make_float2(c[0]+bm0, c[1]+bm0);
                *(float2*)&CpF[(size_t)(m+8) * Ln + n] = make_float2(c[2]+bm1, c[3]+bm1);
            }
        }
    }
}

// ---------------- f32 -> bf16 convert ----------------------------------------
__global__ void cvt_bf16_kernel(const float* __restrict__ in, __nv_bfloat16* __restrict__ out, int n) {
    int i = (blockIdx.x * blockDim.x + threadIdx.x) * 4;
    if (i < n) {
        float4 v = *(const float4*)(in + i);
        *(__nv_bfloat162*)(out + i)     = __floats2bfloat162_rn(v.x, v.y);
        *(__nv_bfloat162*)(out + i + 2) = __floats2bfloat162_rn(v.z, v.w);
    }
}

// concat [a(512) ; b(512)] -> o(1024)
__global__ void concat_bias_kernel(const float* __restrict__ a, const float* __restrict__ b,
                                   float* __restrict__ o) {
    int i = blockIdx.x * 256 + threadIdx.x;
    o[i] = (i < Cn) ? a[i] : b[i - Cn];
}

// ---------------- tiled transpose: xn (B,L,C) -> xnT (B,C,L) -----------------
__global__ void transpose_kernel(const float* __restrict__ in, float* __restrict__ out) {
    __shared__ float t[32][33];
    int z = blockIdx.z;
    int l0 = blockIdx.x * 32, c0 = blockIdx.y * 32;
    int tx = threadIdx.x, ty = threadIdx.y;
    const float* ip = in + (size_t)z * Ln * Cn;
    float* op = out + (size_t)z * Cn * Ln;
    #pragma unroll
    for (int k = 0; k < 4; k++)
        t[ty + 8*k][tx] = ip[(size_t)(l0 + ty + 8*k) * Cn + c0 + tx];
    __syncthreads();
    #pragma unroll
    for (int k = 0; k < 4; k++)
        op[(size_t)(c0 + ty + 8*k) * Ln + l0 + tx] = t[tx][ty + 8*k];
}

// ---------------- LayerNorm: bf16 out (+ optional f32 copy) ------------------
__global__ void ln_kernel(const float* __restrict__ in, const float* __restrict__ w,
                          const float* __restrict__ b, __nv_bfloat16* __restrict__ outb,
                          float* __restrict__ outf) {
    __shared__ float s8[8];
    int row = blockIdx.x, t = threadIdx.x;
    size_t base = (size_t)row * Cn;
    float v0 = in[base + t], v1 = in[base + t + 256];
    float mean = blockReduceSum256(v0 + v1, s8, t) * (1.0f / Cn);
    float d0 = v0 - mean, d1 = v1 - mean;
    float var = blockReduceSum256(d0*d0 + d1*d1, s8, t) * (1.0f / Cn);
    float rs = rsqrtf(var + 1e-5f);
    float o0 = d0 * rs * w[t]       + b[t];
    float o1 = d1 * rs * w[t + 256] + b[t + 256];
    outb[base + t]       = __float2bfloat16_rn(o0);
    outb[base + t + 256] = __float2bfloat16_rn(o1);
    if (outf) { outf[base + t] = o0; outf[base + t + 256] = o1; }
}

// x1 = attn_flat + xnT_flat + x ; x1n = LN(x1) (bf16)
__global__ void x1_ln_kernel(const float* __restrict__ attn, const float* __restrict__ xnT,
                             const float* __restrict__ x,
                             const float* __restrict__ w, const float* __restrict__ b,
                             float* __restrict__ x1, __nv_bfloat16* __restrict__ x1nb) {
    __shared__ float s8[8];
    int row = blockIdx.x, t = threadIdx.x;
    size_t base = (size_t)row * Cn;
    float v0 = attn[base + t]       + xnT[base + t]       + x[base + t];
    float v1 = attn[base + t + 256] + xnT[base + t + 256] + x[base + t + 256];
    x1[base + t] = v0; x1[base + t + 256] = v1;
    float mean = blockReduceSum256(v0 + v1, s8, t) * (1.0f / Cn);
    float d0 = v0 - mean, d1 = v1 - mean;
    float var = blockReduceSum256(d0*d0 + d1*d1, s8, t) * (1.0f / Cn);
    float rs = rsqrtf(var + 1e-5f);
    x1nb[base + t]       = __float2bfloat16_rn(d0 * rs * w[t]       + b[t]);
    x1nb[base + t + 256] = __float2bfloat16_rn(d1 * rs * w[t + 256] + b[t + 256]);
}

// ---------------- k stats: per (b, ck) online max + sumexp over L ------------
__global__ void k_stats(const __nv_bfloat16* __restrict__ kvb,
                        float* __restrict__ kmax, float* __restrict__ kinv) {
    __shared__ float sm[32][8], ss[32][8];
    int tx = threadIdx.x, ty = threadIdx.y;
    int ck = blockIdx.x * 8 + tx;
    int b  = blockIdx.y;
    size_t base = (size_t)b * Ln * CKV + ck;

    float m = -1e30f, s = 0.f;
    for (int l = ty; l < Ln; l += 32) {
        float v = __bfloat162float(kvb[base + (size_t)l * CKV]);
        if (v > m) { s = s * __expf(m - v) + 1.0f; m = v; }
        else        s += __expf(v - m);
    }
    sm[ty][tx] = m; ss[ty][tx] = s;
    __syncthreads();
    #pragma unroll
    for (int st = 16; st > 0; st >>= 1) {
        if (ty < st) {
            float m2 = sm[ty + st][tx], s2 = ss[ty + st][tx];
            float M = fmaxf(sm[ty][tx], m2);
            ss[ty][tx] = ss[ty][tx] * __expf(sm[ty][tx] - M) + s2 * __expf(m2 - M);
            sm[ty][tx] = M;
        }
        __syncthreads();
    }
    if (ty == 0) {
        kmax[b * Cn + ck] = sm[0][tx];
        kinv[b * Cn + ck] = 1.0f / ss[0][tx];
    }
}

__global__ void zero_kernel(float* __restrict__ p, int n) {
    int i = blockIdx.x * blockDim.x + threadIdx.x;
    if (i < n) p[i] = 0.f;
}

// ------- context[b,h,k,v] += sum_l softmax_l(k) * val (exp inline, bf16 in) --
__global__ __launch_bounds__(256)
void context_kernel(const __nv_bfloat16* __restrict__ kvb,
                    const float* __restrict__ kmax, const float* __restrict__ kinv,
                    float* __restrict__ ctx) {
    __shared__ float sK[8][64];
    __shared__ float sV[8][64];
    int b = blockIdx.z, h = blockIdx.y;
    int l0 = blockIdx.x * (Ln / 16);
    int tid = threadIdx.x;
    int tx = tid & 15, ty = tid >> 4;
    int li = tid >> 5, cc = tid & 31;

    float mA = kmax[b * Cn + h * DK + cc];
    float mB = kmax[b * Cn + h * DK + cc + 32];

    float acc[4][4] = {};
    for (int lc = l0; lc < l0 + Ln / 16; lc += 8) {
        size_t idx = ((size_t)(b * Ln + lc + li)) * CKV + h * DK + cc;
        sK[li][cc]      = __expf(__bfloat162float(kvb[idx])      - mA);
        sK[li][cc + 32] = __expf(__bfloat162float(kvb[idx + 32]) - mB);
        sV[li][cc]      = __bfloat162float(kvb[idx + Cn]);
        sV[li][cc + 32] = __bfloat162float(kvb[idx + Cn + 32]);
        __syncthreads();
        #pragma unroll
        for (int l = 0; l < 8; l++) {
            float kvv[4], vv[4];
            #pragma unroll
            for (int i = 0; i < 4; i++) { kvv[i] = sK[l][ty*4+i]; vv[i] = sV[l][tx*4+i]; }
            #pragma unroll
            for (int i = 0; i < 4; i++)
                #pragma unroll
                for (int j = 0; j < 4; j++) acc[i][j] = fmaf(kvv[i], vv[j], acc[i][j]);
        }
        __syncthreads();
    }
    size_t cb = (size_t)(b * Hn + h) * DK * DK;
    #pragma unroll
    for (int i = 0; i < 4; i++) {
        float zi = kinv[b * Cn + h * DK + ty*4 + i];
        #pragma unroll
        for (int j = 0; j < 4; j++)
            atomicAdd(&ctx[cb + (size_t)(ty*4+i) * DK + tx*4+j], acc[i][j] * zi);
    }
}

// ---- aggT[b, l, h*64+v] = sum_k ctx[b,h,k,v] * softmax_k(q[b,l,h,:]) -------
__global__ __launch_bounds__(256)
void agg_kernel(const __nv_bfloat16* __restrict__ qb, const float* __restrict__ ctx,
                __nv_bfloat16* __restrict__ aggT) {
    __shared__ float sC[64][64];
    __shared__ float sQ[128][65];   // padded: conflict-free row access
    int b = blockIdx.z, h = blockIdx.y, l0 = blockIdx.x * 128;
    int tid = threadIdx.x;
    int tx = tid & 15, ty = tid >> 4;

    size_t cb = (size_t)(b * Hn + h) * DK * DK;
    for (int f = tid; f < 4096; f += 256) sC[f >> 6][f & 63] = ctx[cb + f];
    for (int f = tid; f < 8192; f += 256) {
        int l = f >> 6, kk = f & 63;
        sQ[l][kk] = __bfloat162float(qb[((size_t)(b * Ln + l0 + l)) * Cn + h * DK + kk]);
    }
    __syncthreads();

    // in-block q softmax over the 64 channels of this head (2 threads/row)
    {
        int r = tid >> 1;
        int off = (tid & 1) * 32;
        float m = -1e30f;
        #pragma unroll
        for (int j = 0; j < 32; j++) m = fmaxf(m, sQ[r][off + j]);
        m = fmaxf(m, __shfl_xor_sync(0xffffffffu, m, 1));
        float s = 0.f;
        #pragma unroll
        for (int j = 0; j < 32; j++) {
            float e = __expf(sQ[r][off + j] - m);
            sQ[r][off + j] = e;
            s += e;
        }
        s += __shfl_xor_sync(0xffffffffu, s, 1);
        float inv = 1.0f / s;
        #pragma unroll
        for (int j = 0; j < 32; j++) sQ[r][off + j] *= inv;
    }
    __syncthreads();

    float acc[4][8] = {};
    #pragma unroll
    for (int k = 0; k < 64; k++) {
        float cv[4], qv[8];
        #pragma unroll
        for (int i = 0; i < 4; i++) cv[i] = sC[k][tx*4+i];
        #pragma unroll
        for (int j = 0; j < 8; j++) qv[j] = sQ[ty*8+j][k];
        #pragma unroll
        for (int i = 0; i < 4; i++)
            #pragma unroll
            for (int j = 0; j < 8; j++) acc[i][j] = fmaf(cv[i], qv[j], acc[i][j]);
    }
    #pragma unroll
    for (int j = 0; j < 8; j++) {
        size_t ob = ((size_t)(b * Ln + l0 + ty*8 + j)) * Cn + h * DK + tx*4;
        *(__nv_bfloat162*)&aggT[ob]     = __floats2bfloat162_rn(acc[0][j], acc[1][j]);
        *(__nv_bfloat162*)&aggT[ob + 2] = __floats2bfloat162_rn(acc[2][j], acc[3][j]);
    }
}

// ---------------- host launcher ---------------------------------------------
extern "C" void kernel_launch(void* const* d_in, const int* in_sizes, int n_in,
                              void* d_out, int out_size) {
    (void)in_sizes; (void)n_in; (void)out_size;
    const float* x     = (const float*)d_in[0];
    const float* v     = (const float*)d_in[1];
    const float* ln1_w = (const float*)d_in[4];
    const float* ln1_b = (const float*)d_in[5];
    const float* lnv_w = (const float*)d_in[6];
    const float* lnv_b = (const float*)d_in[7];
    const float* ln2_w = (const float*)d_in[8];
    const float* ln2_b = (const float*)d_in[9];
    const float* wq    = (const float*)d_in[10];
    const float* bq    = (const float*)d_in[11];
    const float* wk    = (const float*)d_in[12];
    const float* bk    = (const float*)d_in[13];
    const float* wv    = (const float*)d_in[14];
    const float* bv    = (const float*)d_in[15];
    const float* wr    = (const float*)d_in[16];
    const float* br    = (const float*)d_in[17];
    const float* fc1_w = (const float*)d_in[18];
    const float* fc1_b = (const float*)d_in[19];
    const float* fc2_w = (const float*)d_in[20];
    const float* fc2_b = (const float*)d_in[21];
    float* out = (float*)d_out;

    float *p_xn, *p_xnT, *p_kmax, *p_kinv, *p_ctx, *p_attn, *p_x1, *p_bkv;
    __nv_bfloat16 *p_xnb, *p_vnb, *p_qb, *p_kvb, *p_aggT, *p_x1nb, *p_h1b;
    __nv_bfloat16 *p_wqb, *p_wkvb, *p_wrb, *p_f1b, *p_f2b;
    cudaGetSymbolAddress((void**)&p_xn,  g_xn);
    cudaGetSymbolAddress((void**)&p_xnT, g_xnT);
    cudaGetSymbolAddress((void**)&p_xnb, g_xnb);
    cudaGetSymbolAddress((void**)&p_vnb, g_vnb);
    cudaGetSymbolAddress((void**)&p_qb,  g_qb);
    cudaGetSymbolAddress((void**)&p_kvb, g_kvb);
    cudaGetSymbolAddress((void**)&p_kmax,g_kmax);
    cudaGetSymbolAddress((void**)&p_kinv,g_kinv);
    cudaGetSymbolAddress((void**)&p_ctx, g_ctx);
    cudaGetSymbolAddress((void**)&p_aggT,g_aggT);
    cudaGetSymbolAddress((void**)&p_attn,g_attn);
    cudaGetSymbolAddress((void**)&p_x1,  g_x1);
    cudaGetSymbolAddress((void**)&p_x1nb,g_x1nb);
    cudaGetSymbolAddress((void**)&p_h1b, g_h1b);
    cudaGetSymbolAddress((void**)&p_wqb, g_wqb);
    cudaGetSymbolAddress((void**)&p_wkvb,g_wkvb);
    cudaGetSymbolAddress((void**)&p_wrb, g_wrb);
    cudaGetSymbolAddress((void**)&p_f1b, g_f1b);
    cudaGetSymbolAddress((void**)&p_f2b, g_f2b);
    cudaGetSymbolAddress((void**)&p_bkv, g_bkv);

    cudaFuncSetAttribute(gemm_bf16<1>, cudaFuncAttributeMaxDynamicSharedMemorySize, SMEM_REQ);
    cudaFuncSetAttribute(gemm_bf16<2>, cudaFuncAttributeMaxDynamicSharedMemorySize, SMEM_REQ);
    cudaFuncSetAttribute(gemm_bf16<4>, cudaFuncAttributeMaxDynamicSharedMemorySize, SMEM_REQ);
    cudaFuncSetAttribute(gemm_bf16<5>, cudaFuncAttributeMaxDynamicSharedMemorySize, SMEM_REQ);

    // 0) weight conversion (f32 -> bf16); wk,wv concatenated
    cvt_bf16_kernel<<<(Cn*Cn/4 + 255)/256, 256>>>(wq, p_wqb, Cn*Cn);
    cvt_bf16_kernel<<<(Cn*Cn/4 + 255)/256, 256>>>(wk, p_wkvb, Cn*Cn);
    cvt_bf16_kernel<<<(Cn*Cn/4 + 255)/256, 256>>>(wv, p_wkvb + (size_t)Cn*Cn, Cn*Cn);
    cvt_bf16_kernel<<<(Cn*Cn/4 + 255)/256, 256>>>(wr, p_wrb, Cn*Cn);
    cvt_bf16_kernel<<<(HID*Cn/4 + 255)/256, 256>>>(fc1_w, p_f1b, HID*Cn);
    cvt_bf16_kernel<<<(Cn*HID/4 + 255)/256, 256>>>(fc2_w, p_f2b, Cn*HID);
    concat_bias_kernel<<<CKV/256, 256>>>(bk, bv, p_bkv);

    // 1) LayerNorms (+ xn transpose for the flat residual)
    ln_kernel<<<Mrows, 256>>>(x, ln1_w, ln1_b, p_xnb, p_xn);
    ln_kernel<<<Mrows, 256>>>(v, lnv_w, lnv_b, p_vnb, nullptr);
    transpose_kernel<<<dim3(Ln/32, Cn/32, Bn), dim3(32, 8)>>>(p_xn, p_xnT);

    // 2) projections: q (N=512, bf16 out), fused k|v (N=1024, bf16 out)
    gemm_bf16<4><<<dim3(Cn / 128, Mrows / 128), 256, SMEM_REQ>>>(
        p_xnb, p_wqb, bq, nullptr, p_qb, Mrows, Cn, Cn);
    gemm_bf16<4><<<dim3(CKV / 128, Mrows / 128), 256, SMEM_REQ>>>(
        p_vnb, p_wkvb, p_bkv, nullptr, p_kvb, Mrows, CKV, Cn);

    // 3) k softmax stats (single pass); exp applied inline in context
    k_stats<<<dim3(Cn / 8, Bn), dim3(8, 32)>>>(p_kvb, p_kmax, p_kinv);

    // 4) context = softmax_l(k)^T @ val
    zero_kernel<<<(Bn*Hn*DK*DK + 255) / 256, 256>>>(p_ctx, Bn*Hn*DK*DK);
    context_kernel<<<dim3(16, Hn, Bn), 256>>>(p_kvb, p_kmax, p_kinv, p_ctx);

    // 5) aggT = (ctx^T @ softmax(q))^T  -> (B, L, C) bf16
    agg_kernel<<<dim3(Ln / 128, Hn, Bn), 256>>>(p_qb, p_ctx, p_aggT);

    // 6) reproj: attn[z,c,l] = wr[c,:]·aggT[z,l,:] + br[c]   (no gather)
    gemm_bf16<5><<<dim3(Ln / 128, Cn / 128, Bn), 256, SMEM_REQ>>>(
        p_wrb, p_aggT, br, nullptr, p_attn, Cn, Ln, Cn);

    // 7) x1 = attn + xnT + x ; x1n = LN(x1)
    x1_ln_kernel<<<Mrows, 256>>>(p_attn, p_xnT, x, ln2_w, ln2_b, p_x1, p_x1nb);

    // 8) MLP
    gemm_bf16<1><<<dim3(HID / 128, Mrows / 128), 256, SMEM_REQ>>>(
        p_x1nb, p_f1b, fc1_b, nullptr, p_h1b, Mrows, HID, Cn);
    gemm_bf16<2><<<dim3(Cn / 128, Mrows / 128), 256, SMEM_REQ>>>(
        p_h1b, p_f2b, fc2_b, p_x1, out, Mrows, Cn, HID);
}